// round 11
// baseline (speedup 1.0000x reference)
#include <cuda_runtime.h>

// GRU scan (SEQ=8192, NIN=NHID=1024), single persistent kernel.
//
// R11 = R10/R9/R8 resubmitted unchanged (broker timeouts every round since
// R4; the audited design needs a measurement before further changes).
//   128 CTAs x 256 threads (1 CTA/SM, co-resident). Warp w of CTA c owns
//   hidden unit j = 8c + w over the FULL k=1024: 16 f32x2 pairs per lane.
//   All weights in registers (96 u64 = 192 regs; ~230 total < 255 grant at
//   256 thr/CTA -> no spills; R4 ncu showed regs=128 cap + L1 20.6% spill
//   traffic, which this removes).
//
// Sync: producers publish h as one tagged word {tag:32 | float_bits:32}
//   via st.relaxed.gpu into ring g_hb[t%4][j]. Consumers poll with
//   ld.relaxed.gpu until tag==expected; tag+payload share one 64-bit word,
//   so single-copy atomicity makes tag-match imply valid payload (one L2
//   round trip; no fences/counters on the critical path). The first poll
//   attempt is issued BEFORE the input-part FMA block so its latency
//   overlaps compute; the retry loop self-corrects if it returned stale.
//   All-to-all h dependency bounds inter-CTA skew to 1 step -> 4-slot ring
//   safe. Tags epoch*8192+t+1, epoch = per-launch ordinal (g_epoch gains
//   exactly 128/launch) -> unique across CUDA-graph replays; zero-init ring
//   and stale slots never match.

#define TT      8192
#define HH      1024
#define NCTA    128
#define OPC     8
#define THREADS 256
#define NP      16          // f32x2 pairs per lane per gate (16*2*32 = 1024)
#define NSLOT   4

typedef unsigned long long u64;
typedef unsigned int       u32;

__device__ u64 g_epoch;               // zero-init; +NCTA per launch
__device__ u64 g_hb[NSLOT][HH];       // tagged h ring (32 KB, static)

__device__ __forceinline__ u64 ld_strong(const u64* p) {
    u64 v;
    asm volatile("ld.relaxed.gpu.global.b64 %0, [%1];" : "=l"(v) : "l"(p) : "memory");
    return v;
}
__device__ __forceinline__ void st_strong(u64* p, u64 v) {
    asm volatile("st.relaxed.gpu.global.b64 [%0], %1;" :: "l"(p), "l"(v) : "memory");
}

#define FMA2(d, a, b, c) \
    asm("fma.rn.f32x2 %0, %1, %2, %3;" : "=l"(d) : "l"(a), "l"(b), "l"(c))

__device__ __forceinline__ float hsum2(u64 v) {
    float2 f = *reinterpret_cast<float2*>(&v);
    return f.x + f.y;
}

// MUFU-based, NaN-safe activations (rel err ~1e-6 vs 1e-3 tolerance).
__device__ __forceinline__ float fast_sigmoid(float x) {
    return __frcp_rn(1.0f + __expf(-x));
}
__device__ __forceinline__ float fast_tanh(float x) {
    return 1.0f - 2.0f * __frcp_rn(1.0f + __expf(2.0f * x));
}

__global__ void __launch_bounds__(THREADS, 1)
gru_scan_kernel(const float* __restrict__ xs,
                const float* __restrict__ w_ih,
                const float* __restrict__ w_hh,
                const float* __restrict__ b,
                const float* __restrict__ bn,
                float* __restrict__ out,     // ys copy 1: [TT][HH]
                float* __restrict__ out2)    // ys copy 2 (may alias copy 1)
{
    __shared__ __align__(16) float sx[2][HH];   // x staging, double buffered
    __shared__ __align__(16) float sh[HH];      // h_{t-1} staging
    __shared__ u64 s_epoch;

    const int tid  = threadIdx.x;
    const int w    = tid >> 5;            // warp 0..7 = output index in CTA
    const int lane = tid & 31;
    const int j    = blockIdx.x * OPC + w;

    // ---- one-time: weights into registers, packed f32x2 ----
    u64 whr[NP], whz[NP], whg[NP];
    u64 wir[NP], wiz[NP], wig[NP];
#pragma unroll
    for (int p = 0; p < NP; p++) {
        size_t e = (size_t)2 * (lane + 32 * p);
        whr[p] = *reinterpret_cast<const u64*>(w_hh + (size_t)(j         ) * HH + e);
        whz[p] = *reinterpret_cast<const u64*>(w_hh + (size_t)(j +     HH) * HH + e);
        whg[p] = *reinterpret_cast<const u64*>(w_hh + (size_t)(j + 2 * HH) * HH + e);
        wir[p] = *reinterpret_cast<const u64*>(w_ih + (size_t)(j         ) * HH + e);
        wiz[p] = *reinterpret_cast<const u64*>(w_ih + (size_t)(j +     HH) * HH + e);
        wig[p] = *reinterpret_cast<const u64*>(w_ih + (size_t)(j + 2 * HH) * HH + e);
    }
    const float br  = b[j];
    const float bz  = b[j + HH];
    const float bg  = b[j + 2 * HH];
    const float bnj = bn[j];
    float hprev = 0.0f;

    const float* xptr = xs + HH + 4 * tid;     // x_{t+1} prefetch source

    // stage x_0
    {
        float4 x0 = *reinterpret_cast<const float4*>(xs + 4 * tid);
        *reinterpret_cast<float4*>(&sx[0][4 * tid]) = x0;
    }

    // ---- per-launch epoch (monotonic => replay-unique tags) ----
    if (tid == 0) {
        u64 old = atomicAdd(&g_epoch, 1ULL);
        s_epoch = old >> 7;                    // launch ordinal (128 adds/launch)
    }
    __syncthreads();
    const u64 tagbase = s_epoch * (u64)TT;     // tag of step t = tagbase + t + 1

    for (int t = 0; t < TT; t++) {
        // prefetch x_{t+1} (hidden under compute + poll)
        float4 xpre = (t + 1 < TT)
            ? *reinterpret_cast<const float4*>(xptr)
            : make_float4(0.0f, 0.0f, 0.0f, 0.0f);

        // ---- issue first poll attempt EARLY (overlaps input FMAs) ----
        const u64* slot = g_hb[(t - 1) & (NSLOT - 1)] + 4 * tid;
        u64 v0 = 0, v1 = 0, v2 = 0, v3 = 0;
        if (t > 0) {
            v0 = ld_strong(slot + 0);
            v1 = ld_strong(slot + 1);
            v2 = ld_strong(slot + 2);
            v3 = ld_strong(slot + 3);
        }

        // ---- input part (independent of h_{t-1}) ----
        const u64* sx64 = reinterpret_cast<const u64*>(sx[t & 1]);
        u64 ar2 = 0, az2 = 0, aig2 = 0, ahg2 = 0;
#pragma unroll
        for (int p = 0; p < NP; p++) {
            u64 x2 = sx64[lane + 32 * p];
            FMA2(ar2,  wir[p], x2, ar2);
            FMA2(az2,  wiz[p], x2, az2);
            FMA2(aig2, wig[p], x2, aig2);
        }

        // ---- gather h_{t-1}: retry until tags match, stage into SMEM ----
        if (t > 0) {
            const u32 want = (u32)(tagbase + (u64)t);   // tag of step t-1
            while ((u32)(v0 >> 32) != want) v0 = ld_strong(slot + 0);
            while ((u32)(v1 >> 32) != want) v1 = ld_strong(slot + 1);
            while ((u32)(v2 >> 32) != want) v2 = ld_strong(slot + 2);
            while ((u32)(v3 >> 32) != want) v3 = ld_strong(slot + 3);

            float4 hv;
            hv.x = __uint_as_float((u32)v0);
            hv.y = __uint_as_float((u32)v1);
            hv.z = __uint_as_float((u32)v2);
            hv.w = __uint_as_float((u32)v3);
            *reinterpret_cast<float4*>(&sh[4 * tid]) = hv;
            __syncthreads();

            const u64* sh64 = reinterpret_cast<const u64*>(sh);
#pragma unroll
            for (int p = 0; p < NP; p++) {
                u64 h2 = sh64[lane + 32 * p];
                FMA2(ar2,  whr[p], h2, ar2);
                FMA2(az2,  whz[p], h2, az2);
                FMA2(ahg2, whg[p], h2, ahg2);
            }
        }

        // ---- collapse f32x2 -> scalar, warp butterfly ----
        float ar  = hsum2(ar2);
        float az  = hsum2(az2);
        float aig = hsum2(aig2);
        float ahg = hsum2(ahg2);
#pragma unroll
        for (int off = 16; off > 0; off >>= 1) {
            ar  += __shfl_xor_sync(0xffffffffu, ar,  off);
            az  += __shfl_xor_sync(0xffffffffu, az,  off);
            aig += __shfl_xor_sync(0xffffffffu, aig, off);
            ahg += __shfl_xor_sync(0xffffffffu, ahg, off);
        }

        // ---- gate math, publish tagged h, store output (lane0/warp) ----
        if (lane == 0) {
            float r  = fast_sigmoid(ar + br);
            float z  = fast_sigmoid(az + bz);
            float g  = fast_tanh(fmaf(r, ahg + bnj, aig + bg));
            float hn = fmaf(z, hprev - g, g);      // (1-z)g + z h
            hprev = hn;

            // publish first (critical path), then the plain output stores
            u64 word = ((tagbase + (u64)t + 1) << 32) | (u64)__float_as_uint(hn);
            st_strong(&g_hb[t & (NSLOT - 1)][j], word);

            size_t o = (size_t)t * HH + j;
            out[o]  = hn;
            out2[o] = hn;
        }

        // stage x_{t+1}; trailing bar protects sh/sx reuse next iteration
        *reinterpret_cast<float4*>(&sx[(t + 1) & 1][4 * tid]) = xpre;
        __syncthreads();
        xptr += HH;
    }
}

extern "C" void kernel_launch(void* const* d_in, const int* in_sizes, int n_in,
                              void* d_out, int out_size) {
    const float* xs   = (const float*)d_in[0];   // [8192,1024]
    const float* w_ih = (const float*)d_in[1];   // [3072,1024]
    const float* w_hh = (const float*)d_in[2];   // [3072,1024]
    const float* b    = (const float*)d_in[3];   // [3072]
    const float* bn   = (const float*)d_in[4];   // [1024]
    float* out = (float*)d_out;

    const size_t TH = (size_t)TT * HH;
    // Reference returns (ys, ys): duplicate if the out buffer holds both.
    float* out2 = ((size_t)out_size >= 2 * TH) ? (out + TH) : out;

    gru_scan_kernel<<<NCTA, THREADS>>>(xs, w_ih, w_hh, b, bn, out, out2);
}